// round 10
// baseline (speedup 1.0000x reference)
#include <cuda_runtime.h>
#include <cuda_pipeline.h>
#include <cstdint>

#define NAG  8192
#define OBSD 64
#define HID  128
#define ACTD 16
#define NCH2 64                     // chunks per K2 CTA (4096 k / 64)

// Scratch (device globals: no allocations allowed)
__device__ float g_h   [NAG * HID];          // fp32 encoder output
__device__ int   g_q4  [(NAG / 4) * HID];    // packed s8 h: word[kg][col]
__device__ float g_msgp[4][NAG * HID];       // partial sums (raw, x1/127 in K3)
__device__ int   g_degp[2][NAG];             // partial degrees

// ---------------------------------------------------------------------------
// K1: h = tanh(obs @ W1 + b1) -> g_h (fp32) + g_q4 (packed s8, scale 127).
// ---------------------------------------------------------------------------
__global__ void __launch_bounds__(256) k1_encoder(const float* __restrict__ obs,
                                                  const float* __restrict__ W1,
                                                  const float* __restrict__ b1) {
    __shared__ __align__(16) float sW1[OBSD * HID];   // 32 KB
    __shared__ float sObs[8][OBSD];
    __shared__ unsigned char sQ[8][HID];
    const int t  = threadIdx.x;
    const int a0 = blockIdx.x * 8;

    #pragma unroll
    for (int i = 0; i < (OBSD * HID) / 256; ++i)
        sW1[i * 256 + t] = W1[i * 256 + t];
    #pragma unroll
    for (int i = 0; i < 2; ++i) {
        int idx = i * 256 + t;
        sObs[idx >> 6][idx & 63] = obs[(size_t)(a0 + (idx >> 6)) * OBSD + (idx & 63)];
    }
    __syncthreads();

    const int w = t >> 5, l = t & 31;
    const int agent = a0 + w;
    float acc0 = 0.f, acc1 = 0.f, acc2 = 0.f, acc3 = 0.f;
    #pragma unroll 8
    for (int k = 0; k < OBSD; ++k) {
        float o = sObs[w][k];
        float4 wv = *reinterpret_cast<const float4*>(&sW1[k * HID + l * 4]);
        acc0 = fmaf(o, wv.x, acc0);
        acc1 = fmaf(o, wv.y, acc1);
        acc2 = fmaf(o, wv.z, acc2);
        acc3 = fmaf(o, wv.w, acc3);
    }
    float4 bb = *reinterpret_cast<const float4*>(&b1[l * 4]);
    float h0 = tanhf(acc0 + bb.x);
    float h1 = tanhf(acc1 + bb.y);
    float h2 = tanhf(acc2 + bb.z);
    float h3 = tanhf(acc3 + bb.w);

    const size_t off = (size_t)agent * HID + l * 4;
    float4 hv; hv.x = h0; hv.y = h1; hv.z = h2; hv.w = h3;
    *reinterpret_cast<float4*>(&g_h[off]) = hv;

    sQ[w][l * 4 + 0] = (unsigned char)(__float2int_rn(h0 * 127.f) & 0xFF);
    sQ[w][l * 4 + 1] = (unsigned char)(__float2int_rn(h1 * 127.f) & 0xFF);
    sQ[w][l * 4 + 2] = (unsigned char)(__float2int_rn(h2 * 127.f) & 0xFF);
    sQ[w][l * 4 + 3] = (unsigned char)(__float2int_rn(h3 * 127.f) & 0xFF);
    __syncthreads();

    const int g   = t >> 7;
    const int col = t & 127;
    unsigned wd = (unsigned)sQ[g * 4 + 0][col]
                | ((unsigned)sQ[g * 4 + 1][col] << 8)
                | ((unsigned)sQ[g * 4 + 2][col] << 16)
                | ((unsigned)sQ[g * 4 + 3][col] << 24);
    g_q4[((a0 >> 2) + g) * HID + col] = (int)wd;
}

// ---------------------------------------------------------------------------
// K2: all-dp4a at the fma-pipe floor. 128 CTAs (64 M-tiles x 2 K-halves),
// 512 threads, M=128, chunk=64 k, 64 chunks. Thread = 8 rows x 8 cols x 8 kg
// (ksub = thread half picks kg 0-7 / 8-15 of each chunk; 4 msg partials).
// Ring-4 cp.async; convert chunk c+1 overlapped with compute chunk c;
// ONE __syncthreads per chunk. B staged in 2 planes -> conflict-free LDS.128.
// ---------------------------------------------------------------------------
#define K2_AS    34816                     // A raw stage: 128 x 272 B
#define K2_BS    8192                      // B stage: 16 kg x 512 B (2 planes)
#define K2_STAGE (K2_AS + K2_BS)           // 43008
#define K2_RING  (4 * K2_STAGE)            // 172032
#define K2_A4B   10240                     // packed A: 128 rows x 80 B
#define K2_SMEM  (K2_RING + 2 * K2_A4B)    // 192512

__global__ void __launch_bounds__(512, 1) k2_msg(const int* __restrict__ adj) {
    extern __shared__ __align__(16) char sm2[];
    __shared__ int sDeg[128];

    const int t    = threadIdx.x;
    const int mt   = blockIdx.x & 63;
    const int half = blockIdx.x >> 6;          // 0..1
    const int m0   = mt * 128;
    const int k0   = half * 4096;
    const int kg0  = half * 1024;
    if (t < 128) sDeg[t] = 0;

    // A copy/convert map: row irow (0..127), 16-int32 group ig (0..3)
    const int irow = t >> 2;
    const int ig   = t & 3;
    const char* gA = reinterpret_cast<const char*>(adj) +
                     (size_t)(m0 + irow) * (NAG * 4) + (size_t)k0 * 4 + ig * 64;
    // B copy map: kg row bkg (0..15), 16B seg bseg (0..31); 2-plane remap
    const int bkg  = t >> 5;
    const int bseg = t & 31;
    const int bdst = bkg * 512 + (bseg & 1) * 256 + (bseg >> 1) * 16;
    const char* gB = reinterpret_cast<const char*>(g_q4) +
                     (size_t)(kg0 + bkg) * (HID * 4) + bseg * 16;

    // compute map: ksub (0..1) x trow (0..15) x tcol (0..15)
    const int ksub = t >> 8;
    const int trow = (t >> 4) & 15;
    const int tcol = t & 15;

    int iacc[8][8];
    #pragma unroll
    for (int r = 0; r < 8; ++r)
        #pragma unroll
        for (int j = 0; j < 8; ++j) iacc[r][j] = 0;

    auto issue_stage = [&](int c) {
        char* st = sm2 + (c & 3) * K2_STAGE;
        const char* ga = gA + (size_t)c * 256;
        const char* gq = gB + (size_t)c * 16 * (HID * 4);
        #pragma unroll
        for (int q = 0; q < 4; ++q)
            __pipeline_memcpy_async(st + irow * 272 + ig * 64 + q * 16, ga + q * 16, 16);
        __pipeline_memcpy_async(st + K2_AS + bdst, gq, 16);
    };

    // convert chunk cc's A-raw (own 16 int32) into A4 buffer, count degree
    int cnt = 0;
    auto do_convert = [&](int cc) {
        const char* sAraw = sm2 + (cc & 3) * K2_STAGE;
        int* sA4 = reinterpret_cast<int*>(sm2 + K2_RING + (cc & 1) * K2_A4B);
        const int4* src = reinterpret_cast<const int4*>(sAraw + irow * 272 + ig * 64);
        int4 v0 = src[0], v1 = src[1], v2 = src[2], v3 = src[3];
        cnt += v0.x + v0.y + v0.z + v0.w + v1.x + v1.y + v1.z + v1.w +
               v2.x + v2.y + v2.z + v2.w + v3.x + v3.y + v3.z + v3.w;
        int4 w;
        w.x = (int)__byte_perm(__byte_perm(v0.x, v0.y, 0x0040),
                               __byte_perm(v0.z, v0.w, 0x0040), 0x5410);
        w.y = (int)__byte_perm(__byte_perm(v1.x, v1.y, 0x0040),
                               __byte_perm(v1.z, v1.w, 0x0040), 0x5410);
        w.z = (int)__byte_perm(__byte_perm(v2.x, v2.y, 0x0040),
                               __byte_perm(v2.z, v2.w, 0x0040), 0x5410);
        w.w = (int)__byte_perm(__byte_perm(v3.x, v3.y, 0x0040),
                               __byte_perm(v3.z, v3.w, 0x0040), 0x5410);
        *reinterpret_cast<int4*>(&sA4[irow * 20 + ig * 4]) = w;
    };

    issue_stage(0); __pipeline_commit();
    issue_stage(1); __pipeline_commit();
    issue_stage(2); __pipeline_commit();
    __pipeline_wait_prior(2);      // stage 0 landed (own copies)
    do_convert(0);
    __syncthreads();               // A4[0] + B stage 0 visible to all

    for (int c = 0; c < NCH2; ++c) {
        if (c + 3 < NCH2) issue_stage(c + 3);
        __pipeline_commit();
        __pipeline_wait_prior(2);  // stage c+1 landed (own copies)
        if (c + 1 < NCH2) do_convert(c + 1);   // overlaps with dp4a below

        // compute chunk c: kg = ksub*8 + 0..7
        const int* A4 = reinterpret_cast<const int*>(sm2 + K2_RING + (c & 1) * K2_A4B);
        const int* B4 = reinterpret_cast<const int*>(sm2 + (c & 3) * K2_STAGE + K2_AS);
        #pragma unroll
        for (int jk = 0; jk < 8; ++jk) {
            const int kg = ksub * 8 + jk;
            int a[8];
            #pragma unroll
            for (int r = 0; r < 8; ++r)
                a[r] = A4[(8 * trow + r) * 20 + kg];
            int4 b0 = *reinterpret_cast<const int4*>(&B4[kg * 128 + tcol * 4]);
            int4 b1 = *reinterpret_cast<const int4*>(&B4[kg * 128 + 64 + tcol * 4]);
            #pragma unroll
            for (int r = 0; r < 8; ++r) {
                iacc[r][0] = __dp4a(a[r], b0.x, iacc[r][0]);
                iacc[r][1] = __dp4a(a[r], b0.y, iacc[r][1]);
                iacc[r][2] = __dp4a(a[r], b0.z, iacc[r][2]);
                iacc[r][3] = __dp4a(a[r], b0.w, iacc[r][3]);
                iacc[r][4] = __dp4a(a[r], b1.x, iacc[r][4]);
                iacc[r][5] = __dp4a(a[r], b1.y, iacc[r][5]);
                iacc[r][6] = __dp4a(a[r], b1.z, iacc[r][6]);
                iacc[r][7] = __dp4a(a[r], b1.w, iacc[r][7]);
            }
        }
        __syncthreads();           // A4[(c+1)&1] visible; stage slot c reusable
    }

    atomicAdd(&sDeg[irow], cnt);

    // write partials straight from registers (raw sums; 1/127 folded in K3)
    float* dst = g_msgp[half * 2 + ksub];
    #pragma unroll
    for (int r = 0; r < 8; ++r) {
        float* p = dst + (size_t)(m0 + 8 * trow + r) * HID + tcol * 8;
        float4 f0, f1;
        f0.x = (float)iacc[r][0]; f0.y = (float)iacc[r][1];
        f0.z = (float)iacc[r][2]; f0.w = (float)iacc[r][3];
        f1.x = (float)iacc[r][4]; f1.y = (float)iacc[r][5];
        f1.z = (float)iacc[r][6]; f1.w = (float)iacc[r][7];
        *reinterpret_cast<float4*>(p)     = f0;
        *reinterpret_cast<float4*>(p + 4) = f1;
    }
    __syncthreads();
    if (t < 128) g_degp[half][m0 + t] = sDeg[t];
}

// ---------------------------------------------------------------------------
// K3: merge 4 partials -> msg; hid = tanh([h,msg]@W2+b2); out = hid@W3+b3.
// ---------------------------------------------------------------------------
#define K3_SMEM (4 * (32768 + 16448 + 2048 + 128 + 16 + 64))   // 205,888 B

__global__ void __launch_bounds__(256, 1) k3_actor(float* __restrict__ out,
        const float* __restrict__ W2, const float* __restrict__ b2,
        const float* __restrict__ W3, const float* __restrict__ b3) {
    extern __shared__ __align__(16) float sm[];
    float* sW2 = sm;                   // [256][128]
    float* sC  = sm + 32768;           // [64][257]; reused as hid [64][129]
    float* sW3 = sC + 16448;           // [128][16]
    float* sb2 = sW3 + 2048;
    float* sb3 = sb2 + 128;
    float* sInv = sb3 + 16;            // [64] 1/(127*deg)

    const int t  = threadIdx.x;
    const int a0 = blockIdx.x * 64;

    #pragma unroll 4
    for (int i = 0; i < 128; ++i) sW2[i * 256 + t] = W2[i * 256 + t];
    #pragma unroll
    for (int i = 0; i < 8; ++i)   sW3[i * 256 + t] = W3[i * 256 + t];
    if (t < 128) sb2[t] = b2[t];
    if (t < 16)  sb3[t] = b3[t];
    if (t < 64) {
        int d = g_degp[0][a0 + t] + g_degp[1][a0 + t];
        sInv[t] = 1.0f / (127.0f * (float)max(d, 1));
    }
    __syncthreads();
    #pragma unroll 4
    for (int i = 0; i < 32; ++i) {
        int idx = i * 256 + t;
        int a = idx >> 7, k = idx & 127;
        size_t o = (size_t)(a0 + a) * HID + k;
        sC[a * 257 + k] = g_h[o];
        float s = g_msgp[0][o] + g_msgp[1][o] + g_msgp[2][o] + g_msgp[3][o];
        sC[a * 257 + 128 + k] = s * sInv[a];
    }
    __syncthreads();

    const int ar = t >> 4;
    const int cc = t & 15;
    float acc[4][8];
    #pragma unroll
    for (int j = 0; j < 4; ++j)
        #pragma unroll
        for (int i = 0; i < 8; ++i) acc[j][i] = 0.f;

    #pragma unroll 2
    for (int k = 0; k < 2 * HID; ++k) {
        float4 w0 = *reinterpret_cast<const float4*>(&sW2[k * 128 + cc * 8]);
        float4 w1 = *reinterpret_cast<const float4*>(&sW2[k * 128 + cc * 8 + 4]);
        #pragma unroll
        for (int j = 0; j < 4; ++j) {
            float cv = sC[(ar * 4 + j) * 257 + k];
            acc[j][0] = fmaf(cv, w0.x, acc[j][0]);
            acc[j][1] = fmaf(cv, w0.y, acc[j][1]);
            acc[j][2] = fmaf(cv, w0.z, acc[j][2]);
            acc[j][3] = fmaf(cv, w0.w, acc[j][3]);
            acc[j][4] = fmaf(cv, w1.x, acc[j][4]);
            acc[j][5] = fmaf(cv, w1.y, acc[j][5]);
            acc[j][6] = fmaf(cv, w1.z, acc[j][6]);
            acc[j][7] = fmaf(cv, w1.w, acc[j][7]);
        }
    }
    __syncthreads();
    float* sH = sC;                       // [64][129]
    #pragma unroll
    for (int j = 0; j < 4; ++j) {
        int a = ar * 4 + j;
        #pragma unroll
        for (int i = 0; i < 8; ++i) {
            int ccol = cc * 8 + i;
            sH[a * 129 + ccol] = tanhf(acc[j][i] + sb2[ccol]);
        }
    }
    __syncthreads();

    const int a  = t >> 2;
    const int cq = t & 3;
    float4 lg; lg.x = 0.f; lg.y = 0.f; lg.z = 0.f; lg.w = 0.f;
    #pragma unroll 8
    for (int k = 0; k < HID; ++k) {
        float hv  = sH[a * 129 + k];
        float4 w3 = *reinterpret_cast<const float4*>(&sW3[k * 16 + cq * 4]);
        lg.x = fmaf(hv, w3.x, lg.x);
        lg.y = fmaf(hv, w3.y, lg.y);
        lg.z = fmaf(hv, w3.z, lg.z);
        lg.w = fmaf(hv, w3.w, lg.w);
    }
    lg.x += sb3[cq * 4 + 0];
    lg.y += sb3[cq * 4 + 1];
    lg.z += sb3[cq * 4 + 2];
    lg.w += sb3[cq * 4 + 3];
    *reinterpret_cast<float4*>(&out[(size_t)(a0 + a) * ACTD + cq * 4]) = lg;
}

// ---------------------------------------------------------------------------
extern "C" void kernel_launch(void* const* d_in, const int* in_sizes, int n_in,
                              void* d_out, int out_size) {
    const float* obs = (const float*)d_in[0];
    const int*   adj = (const int*)  d_in[1];
    const float* W1  = (const float*)d_in[2];
    const float* b1  = (const float*)d_in[3];
    const float* W2  = (const float*)d_in[4];
    const float* b2  = (const float*)d_in[5];
    const float* W3  = (const float*)d_in[6];
    const float* b3  = (const float*)d_in[7];
    float* out = (float*)d_out;

    cudaFuncSetAttribute(k2_msg,   cudaFuncAttributeMaxDynamicSharedMemorySize, K2_SMEM);
    cudaFuncSetAttribute(k3_actor, cudaFuncAttributeMaxDynamicSharedMemorySize, K3_SMEM);

    k1_encoder<<<NAG / 8, 256>>>(obs, W1, b1);
    k2_msg    <<<128, 512, K2_SMEM>>>(adj);
    k3_actor  <<<NAG / 64, 256, K3_SMEM>>>(out, W2, b2, W3, b3);
}

// round 11
// speedup vs baseline: 1.1409x; 1.1409x over previous
#include <cuda_runtime.h>
#include <cuda_bf16.h>
#include <cuda_pipeline.h>
#include <mma.h>
#include <cstdint>

using namespace nvcuda;

#define NAG  8192
#define OBSD 64
#define HID  128
#define ACTD 16
#define NITEMS 1024        // 128 M-tiles x 8 k-quarters
#define GRID2  148         // persistent CTAs = SM count
#define NCHI   16          // chunks per item (1024 k / 64)

// Scratch (device globals: no allocations allowed)
__device__ float          g_h   [NAG * HID];       // fp32 encoder output
__device__ __nv_bfloat16  g_hb  [NAG * HID];       // bf16 h (row-major)
__device__ float          g_msgp[8][NAG * HID];    // per-k-quarter partial sums
__device__ int            g_degp[8][NAG];          // per-k-quarter degrees

// ---------------------------------------------------------------------------
// K1: h = tanh(obs @ W1 + b1) -> g_h (fp32) + g_hb (bf16).
// 1024 CTAs x 256 threads; one warp per agent.
// ---------------------------------------------------------------------------
__global__ void __launch_bounds__(256) k1_encoder(const float* __restrict__ obs,
                                                  const float* __restrict__ W1,
                                                  const float* __restrict__ b1) {
    __shared__ __align__(16) float sW1[OBSD * HID];   // 32 KB
    __shared__ float sObs[8][OBSD];
    const int t  = threadIdx.x;
    const int a0 = blockIdx.x * 8;

    #pragma unroll
    for (int i = 0; i < (OBSD * HID) / 256; ++i)
        sW1[i * 256 + t] = W1[i * 256 + t];
    #pragma unroll
    for (int i = 0; i < 2; ++i) {
        int idx = i * 256 + t;
        sObs[idx >> 6][idx & 63] = obs[(size_t)(a0 + (idx >> 6)) * OBSD + (idx & 63)];
    }
    __syncthreads();

    const int w = t >> 5, l = t & 31;
    const int agent = a0 + w;
    float acc0 = 0.f, acc1 = 0.f, acc2 = 0.f, acc3 = 0.f;
    #pragma unroll 8
    for (int k = 0; k < OBSD; ++k) {
        float o = sObs[w][k];
        float4 wv = *reinterpret_cast<const float4*>(&sW1[k * HID + l * 4]);
        acc0 = fmaf(o, wv.x, acc0);
        acc1 = fmaf(o, wv.y, acc1);
        acc2 = fmaf(o, wv.z, acc2);
        acc3 = fmaf(o, wv.w, acc3);
    }
    float4 bb = *reinterpret_cast<const float4*>(&b1[l * 4]);
    float h0 = tanhf(acc0 + bb.x);
    float h1 = tanhf(acc1 + bb.y);
    float h2 = tanhf(acc2 + bb.z);
    float h3 = tanhf(acc3 + bb.w);

    const size_t off = (size_t)agent * HID + l * 4;
    float4 hv; hv.x = h0; hv.y = h1; hv.z = h2; hv.w = h3;
    *reinterpret_cast<float4*>(&g_h[off]) = hv;
    __nv_bfloat162 p0 = __floats2bfloat162_rn(h0, h1);
    __nv_bfloat162 p1 = __floats2bfloat162_rn(h2, h3);
    *reinterpret_cast<__nv_bfloat162*>(&g_hb[off])     = p0;
    *reinterpret_cast<__nv_bfloat162*>(&g_hb[off + 2]) = p1;
}

// no-op spacers: shift ncu's captured launch (-s 5 -c 1) onto k2_msg
__global__ void knop() {}

// ---------------------------------------------------------------------------
// K2: msg partials via bf16 WMMA, persistent 148 CTAs, static item list.
// Item = (mt, kq): 64 rows x 1024 k (16 chunks of 64). CTA b -> items b+148i.
// Staging/convert identical to round-5 best: ring-4 cp.async {A raw 17408B,
// B bf16 17408B}, converted-A double buffer, ONE main barrier per chunk.
// 8 warps: wm(2 x 32 rows) x wn(4 x 32 cols), all 4 ks per warp.
// Per-item epilogue: fragment store straight to g_msgp[kq] (disjoint rows).
// ---------------------------------------------------------------------------
__device__ __forceinline__ unsigned pack2i(int a, int b) {
    return (a ? 0x3F80u : 0u) | (b ? 0x3F800000u : 0u);   // two bf16 {0,1}
}

#define K2_AS    17408                     // A raw: 64 x 272 B
#define K2_BS    17408                     // B bf16: 64 x 272 B
#define K2_STAGE (K2_AS + K2_BS)           // 34816
#define K2_RING  (4 * K2_STAGE)            // 139264
#define K2_ABF   9216                      // converted A: 64 x 144 B
#define K2_SMEM  (K2_RING + 2 * K2_ABF)    // 157696

__global__ void __launch_bounds__(256, 1) k2_msg(const int* __restrict__ adj) {
    extern __shared__ __align__(16) char sm2[];
    __shared__ int sDeg[64];

    const int t   = threadIdx.x;
    const int wid = t >> 5;
    const int irow = t >> 2;       // 0..63 (A row & B k-row)
    const int ig   = t & 3;        // 64B quarter
    const int wm = wid & 1;        // M block (32 rows)
    const int wn = wid >> 1;       // N block (32 cols), 0..3

    for (int item = blockIdx.x; item < NITEMS; item += GRID2) {
        const int mt = item & 127;
        const int kq = item >> 7;
        const int m0 = mt * 64;
        const int k0 = kq * 1024;

        const char* gA = reinterpret_cast<const char*>(adj) +
                         (size_t)(m0 + irow) * (NAG * 4) + (size_t)k0 * 4 + ig * 64;
        const char* gB = reinterpret_cast<const char*>(g_hb) +
                         (size_t)(k0 + irow) * (HID * 2) + ig * 64;

        if (t < 64) sDeg[t] = 0;
        int cnt = 0;

        wmma::fragment<wmma::accumulator, 16, 16, 16, float> acc[2][2];
        #pragma unroll
        for (int i = 0; i < 2; ++i)
            #pragma unroll
            for (int j = 0; j < 2; ++j)
                wmma::fill_fragment(acc[i][j], 0.0f);

        auto issue_stage = [&](int c) {
            char* st = sm2 + (c & 3) * K2_STAGE;
            const char* ga = gA + (size_t)c * 256;          // 64 int32 per row
            const char* gb = gB + (size_t)c * 64 * 256;     // 64 k-rows x 256B
            #pragma unroll
            for (int q = 0; q < 4; ++q)
                __pipeline_memcpy_async(st + irow * 272 + ig * 64 + q * 16,
                                        ga + q * 16, 16);
            #pragma unroll
            for (int q = 0; q < 4; ++q)
                __pipeline_memcpy_async(st + K2_AS + irow * 272 + ig * 64 + q * 16,
                                        gb + q * 16, 16);
        };

        auto do_convert = [&](int cc) {
            const char* sAraw = sm2 + (cc & 3) * K2_STAGE;
            char* sAbf = sm2 + K2_RING + (cc & 1) * K2_ABF;
            const int4* src = reinterpret_cast<const int4*>(sAraw + irow * 272 + ig * 64);
            int4 v0 = src[0], v1 = src[1], v2 = src[2], v3 = src[3];
            cnt += v0.x + v0.y + v0.z + v0.w + v1.x + v1.y + v1.z + v1.w +
                   v2.x + v2.y + v2.z + v2.w + v3.x + v3.y + v3.z + v3.w;
            uint4 w0, w1;
            w0.x = pack2i(v0.x, v0.y); w0.y = pack2i(v0.z, v0.w);
            w0.z = pack2i(v1.x, v1.y); w0.w = pack2i(v1.z, v1.w);
            w1.x = pack2i(v2.x, v2.y); w1.y = pack2i(v2.z, v2.w);
            w1.z = pack2i(v3.x, v3.y); w1.w = pack2i(v3.z, v3.w);
            uint4* dst = reinterpret_cast<uint4*>(sAbf + irow * 144 + ig * 32);
            dst[0] = w0; dst[1] = w1;
        };

        issue_stage(0); __pipeline_commit();
        issue_stage(1); __pipeline_commit();
        issue_stage(2); __pipeline_commit();
        __pipeline_wait_prior(2);          // stage 0 landed (own copies)
        do_convert(0);
        __syncthreads();                   // Abf[0] + B stage 0 visible

        for (int c = 0; c < NCHI; ++c) {
            if (c + 3 < NCHI) issue_stage(c + 3);
            __pipeline_commit();
            __pipeline_wait_prior(2);      // stage c+1 landed (own copies)
            if (c + 1 < NCHI) do_convert(c + 1);

            const __nv_bfloat16* A =
                reinterpret_cast<const __nv_bfloat16*>(sm2 + K2_RING + (c & 1) * K2_ABF);
            const __nv_bfloat16* B =
                reinterpret_cast<const __nv_bfloat16*>(sm2 + (c & 3) * K2_STAGE + K2_AS);
            #pragma unroll
            for (int ks = 0; ks < 4; ++ks) {
                wmma::fragment<wmma::matrix_a, 16, 16, 16, __nv_bfloat16, wmma::row_major> af[2];
                wmma::fragment<wmma::matrix_b, 16, 16, 16, __nv_bfloat16, wmma::row_major> bf[2];
                #pragma unroll
                for (int i = 0; i < 2; ++i)
                    wmma::load_matrix_sync(af[i], &A[(wm * 32 + i * 16) * 72 + ks * 16], 72);
                #pragma unroll
                for (int j = 0; j < 2; ++j)
                    wmma::load_matrix_sync(bf[j], &B[(ks * 16) * 136 + wn * 32 + j * 16], 136);
                #pragma unroll
                for (int i = 0; i < 2; ++i)
                    #pragma unroll
                    for (int j = 0; j < 2; ++j)
                        wmma::mma_sync(acc[i][j], af[i], bf[j], acc[i][j]);
            }
            __syncthreads();               // Abf[(c+1)&1] + stage reuse safe
        }

        atomicAdd(&sDeg[irow], cnt);

        // fragment store straight to this item's partial (disjoint rows)
        float* dst = g_msgp[kq];
        #pragma unroll
        for (int i = 0; i < 2; ++i)
            #pragma unroll
            for (int j = 0; j < 2; ++j)
                wmma::store_matrix_sync(
                    &dst[(size_t)(m0 + wm * 32 + i * 16) * HID + wn * 32 + j * 16],
                    acc[i][j], HID, wmma::mem_row_major);

        __syncthreads();
        if (t < 64) g_degp[kq][m0 + t] = sDeg[t];
        __syncthreads();                   // sDeg reads done before next item's zeroing
    }
}

// ---------------------------------------------------------------------------
// K3: merge 8 partials -> msg; hid = tanh([h,msg]@W2+b2); out = hid@W3+b3.
// ---------------------------------------------------------------------------
#define K3_SMEM (4 * (32768 + 16448 + 2048 + 128 + 16 + 64))   // 205,888 B

__global__ void __launch_bounds__(256, 1) k3_actor(float* __restrict__ out,
        const float* __restrict__ W2, const float* __restrict__ b2,
        const float* __restrict__ W3, const float* __restrict__ b3) {
    extern __shared__ __align__(16) float sm[];
    float* sW2 = sm;                   // [256][128]
    float* sC  = sm + 32768;           // [64][257]; reused as hid [64][129]
    float* sW3 = sC + 16448;           // [128][16]
    float* sb2 = sW3 + 2048;
    float* sb3 = sb2 + 128;
    float* sInv = sb3 + 16;            // [64] 1/deg

    const int t  = threadIdx.x;
    const int a0 = blockIdx.x * 64;

    #pragma unroll 4
    for (int i = 0; i < 128; ++i) sW2[i * 256 + t] = W2[i * 256 + t];
    #pragma unroll
    for (int i = 0; i < 8; ++i)   sW3[i * 256 + t] = W3[i * 256 + t];
    if (t < 128) sb2[t] = b2[t];
    if (t < 16)  sb3[t] = b3[t];
    if (t < 64) {
        int d = 0;
        #pragma unroll
        for (int p = 0; p < 8; ++p) d += g_degp[p][a0 + t];
        sInv[t] = 1.0f / (float)max(d, 1);
    }
    __syncthreads();
    #pragma unroll 4
    for (int i = 0; i < 32; ++i) {
        int idx = i * 256 + t;
        int a = idx >> 7, k = idx & 127;
        size_t o = (size_t)(a0 + a) * HID + k;
        sC[a * 257 + k] = g_h[o];
        float s = 0.f;
        #pragma unroll
        for (int p = 0; p < 8; ++p) s += g_msgp[p][o];
        sC[a * 257 + 128 + k] = s * sInv[a];
    }
    __syncthreads();

    const int ar = t >> 4;
    const int cc = t & 15;
    float acc[4][8];
    #pragma unroll
    for (int j = 0; j < 4; ++j)
        #pragma unroll
        for (int i = 0; i < 8; ++i) acc[j][i] = 0.f;

    #pragma unroll 2
    for (int k = 0; k < 2 * HID; ++k) {
        float4 w0 = *reinterpret_cast<const float4*>(&sW2[k * 128 + cc * 8]);
        float4 w1 = *reinterpret_cast<const float4*>(&sW2[k * 128 + cc * 8 + 4]);
        #pragma unroll
        for (int j = 0; j < 4; ++j) {
            float cv = sC[(ar * 4 + j) * 257 + k];
            acc[j][0] = fmaf(cv, w0.x, acc[j][0]);
            acc[j][1] = fmaf(cv, w0.y, acc[j][1]);
            acc[j][2] = fmaf(cv, w0.z, acc[j][2]);
            acc[j][3] = fmaf(cv, w0.w, acc[j][3]);
            acc[j][4] = fmaf(cv, w1.x, acc[j][4]);
            acc[j][5] = fmaf(cv, w1.y, acc[j][5]);
            acc[j][6] = fmaf(cv, w1.z, acc[j][6]);
            acc[j][7] = fmaf(cv, w1.w, acc[j][7]);
        }
    }
    __syncthreads();
    float* sH = sC;                       // [64][129]
    #pragma unroll
    for (int j = 0; j < 4; ++j) {
        int a = ar * 4 + j;
        #pragma unroll
        for (int i = 0; i < 8; ++i) {
            int ccol = cc * 8 + i;
            sH[a * 129 + ccol] = tanhf(acc[j][i] + sb2[ccol]);
        }
    }
    __syncthreads();

    const int a  = t >> 2;
    const int cq = t & 3;
    float4 lg; lg.x = 0.f; lg.y = 0.f; lg.z = 0.f; lg.w = 0.f;
    #pragma unroll 8
    for (int k = 0; k < HID; ++k) {
        float hv  = sH[a * 129 + k];
        float4 w3 = *reinterpret_cast<const float4*>(&sW3[k * 16 + cq * 4]);
        lg.x = fmaf(hv, w3.x, lg.x);
        lg.y = fmaf(hv, w3.y, lg.y);
        lg.z = fmaf(hv, w3.z, lg.z);
        lg.w = fmaf(hv, w3.w, lg.w);
    }
    lg.x += sb3[cq * 4 + 0];
    lg.y += sb3[cq * 4 + 1];
    lg.z += sb3[cq * 4 + 2];
    lg.w += sb3[cq * 4 + 3];
    *reinterpret_cast<float4*>(&out[(size_t)(a0 + a) * ACTD + cq * 4]) = lg;
}

// ---------------------------------------------------------------------------
extern "C" void kernel_launch(void* const* d_in, const int* in_sizes, int n_in,
                              void* d_out, int out_size) {
    const float* obs = (const float*)d_in[0];
    const int*   adj = (const int*)  d_in[1];
    const float* W1  = (const float*)d_in[2];
    const float* b1  = (const float*)d_in[3];
    const float* W2  = (const float*)d_in[4];
    const float* b2  = (const float*)d_in[5];
    const float* W3  = (const float*)d_in[6];
    const float* b3  = (const float*)d_in[7];
    float* out = (float*)d_out;

    cudaFuncSetAttribute(k2_msg,   cudaFuncAttributeMaxDynamicSharedMemorySize, K2_SMEM);
    cudaFuncSetAttribute(k3_actor, cudaFuncAttributeMaxDynamicSharedMemorySize, K3_SMEM);

    k1_encoder<<<NAG / 8, 256>>>(obs, W1, b1);
    knop<<<1, 32>>>();                 // spacers: land ncu capture on k2_msg
    knop<<<1, 32>>>();
    k2_msg    <<<GRID2, 256, K2_SMEM>>>(adj);
    k3_actor  <<<NAG / 64, 256, K3_SMEM>>>(out, W2, b2, W3, b3);
}

// round 12
// speedup vs baseline: 1.3177x; 1.1550x over previous
#include <cuda_runtime.h>
#include <cuda_bf16.h>
#include <cuda_pipeline.h>
#include <mma.h>
#include <cstdint>

using namespace nvcuda;

#define NAG  8192
#define OBSD 64
#define HID  128
#define ACTD 16
#define NITEMS 1024        // 128 M-tiles x 8 k-quarters
#define GRID2  148         // persistent CTAs = SM count
#define NCHI   16          // chunks per item (1024 k / 64)

// Scratch (device globals: no allocations allowed)
__device__ float          g_h   [NAG * HID];       // fp32 encoder output
__device__ __nv_bfloat16  g_hb  [NAG * HID];       // bf16 h (row-major)
__device__ float          g_msgp[8][NAG * HID];    // per-k-quarter partial sums
__device__ int            g_degp[8][NAG];          // per-k-quarter degrees

// ---------------------------------------------------------------------------
// K1: h = tanh(obs @ W1 + b1) -> g_h (fp32) + g_hb (bf16).
// ---------------------------------------------------------------------------
__global__ void __launch_bounds__(256) k1_encoder(const float* __restrict__ obs,
                                                  const float* __restrict__ W1,
                                                  const float* __restrict__ b1) {
    __shared__ __align__(16) float sW1[OBSD * HID];   // 32 KB
    __shared__ float sObs[8][OBSD];
    const int t  = threadIdx.x;
    const int a0 = blockIdx.x * 8;

    #pragma unroll
    for (int i = 0; i < (OBSD * HID) / 256; ++i)
        sW1[i * 256 + t] = W1[i * 256 + t];
    #pragma unroll
    for (int i = 0; i < 2; ++i) {
        int idx = i * 256 + t;
        sObs[idx >> 6][idx & 63] = obs[(size_t)(a0 + (idx >> 6)) * OBSD + (idx & 63)];
    }
    __syncthreads();

    const int w = t >> 5, l = t & 31;
    const int agent = a0 + w;
    float acc0 = 0.f, acc1 = 0.f, acc2 = 0.f, acc3 = 0.f;
    #pragma unroll 8
    for (int k = 0; k < OBSD; ++k) {
        float o = sObs[w][k];
        float4 wv = *reinterpret_cast<const float4*>(&sW1[k * HID + l * 4]);
        acc0 = fmaf(o, wv.x, acc0);
        acc1 = fmaf(o, wv.y, acc1);
        acc2 = fmaf(o, wv.z, acc2);
        acc3 = fmaf(o, wv.w, acc3);
    }
    float4 bb = *reinterpret_cast<const float4*>(&b1[l * 4]);
    float h0 = tanhf(acc0 + bb.x);
    float h1 = tanhf(acc1 + bb.y);
    float h2 = tanhf(acc2 + bb.z);
    float h3 = tanhf(acc3 + bb.w);

    const size_t off = (size_t)agent * HID + l * 4;
    float4 hv; hv.x = h0; hv.y = h1; hv.z = h2; hv.w = h3;
    *reinterpret_cast<float4*>(&g_h[off]) = hv;
    __nv_bfloat162 p0 = __floats2bfloat162_rn(h0, h1);
    __nv_bfloat162 p1 = __floats2bfloat162_rn(h2, h3);
    *reinterpret_cast<__nv_bfloat162*>(&g_hb[off])     = p0;
    *reinterpret_cast<__nv_bfloat162*>(&g_hb[off + 2]) = p1;
}

// no-op spacers: shift ncu's captured launch (-s 5 -c 1) onto k2_msg
__global__ void knop() {}

// ---------------------------------------------------------------------------
// K2: msg partials via bf16 WMMA, persistent 148 CTAs, static item list.
// 512 threads = 16 warps (4/SMSP) to cover LDSM/HMMA latency (R11 profile:
// tensor 15.8%, issue 16.1%, occ 12.5% -> latency-bound, not pipe-bound).
// Warp = wm(2 x 32 rows) x wn(4 x 32 cols) x kh(2 x 2ks): dep chain halves,
// 4 independent acc chains/warp. kh partials merged in item epilogue.
// Ring-4 cp.async {A raw 64x272B, B bf16 64x272B}; ONE barrier per chunk.
// ---------------------------------------------------------------------------
__device__ __forceinline__ unsigned pack2i(int a, int b) {
    return (a ? 0x3F80u : 0u) | (b ? 0x3F800000u : 0u);   // two bf16 {0,1}
}

#define K2_AS    17408                     // A raw: 64 x 272 B
#define K2_BS    17408                     // B bf16: 64 x 272 B
#define K2_STAGE (K2_AS + K2_BS)           // 34816
#define K2_RING  (4 * K2_STAGE)            // 139264
#define K2_ABF   9216                      // converted A: 64 x 144 B
#define K2_SMEM  (K2_RING + 2 * K2_ABF)    // 157696

__global__ void __launch_bounds__(512, 1) k2_msg(const int* __restrict__ adj) {
    extern __shared__ __align__(16) char sm2[];
    __shared__ int sDeg[64];

    const int t    = threadIdx.x;
    const int wid  = t >> 5;
    const int irow = t >> 3;       // 0..63 (A row & B k-row)
    const int ig8  = t & 7;        // 32B group within row
    const int wm   = wid & 1;          // M block (32 rows)
    const int wn   = (wid >> 1) & 3;   // N block (32 cols)
    const int kh   = wid >> 3;         // ks half (0: ks 0-1, 1: ks 2-3)

    for (int item = blockIdx.x; item < NITEMS; item += GRID2) {
        const int mt = item & 127;
        const int kq = item >> 7;
        const int m0 = mt * 64;
        const int k0 = kq * 1024;

        const char* gA = reinterpret_cast<const char*>(adj) +
                         (size_t)(m0 + irow) * (NAG * 4) + (size_t)k0 * 4 + ig8 * 32;
        const char* gB = reinterpret_cast<const char*>(g_hb) +
                         (size_t)(k0 + irow) * (HID * 2) + ig8 * 32;

        if (t < 64) sDeg[t] = 0;
        int cnt = 0;

        wmma::fragment<wmma::accumulator, 16, 16, 16, float> acc[2][2];
        #pragma unroll
        for (int i = 0; i < 2; ++i)
            #pragma unroll
            for (int j = 0; j < 2; ++j)
                wmma::fill_fragment(acc[i][j], 0.0f);

        auto issue_stage = [&](int c) {
            char* st = sm2 + (c & 3) * K2_STAGE;
            const char* ga = gA + (size_t)c * 256;          // 64 int32 per row
            const char* gb = gB + (size_t)c * 64 * 256;     // 64 k-rows x 256B
            #pragma unroll
            for (int q = 0; q < 2; ++q)
                __pipeline_memcpy_async(st + irow * 272 + ig8 * 32 + q * 16,
                                        ga + q * 16, 16);
            #pragma unroll
            for (int q = 0; q < 2; ++q)
                __pipeline_memcpy_async(st + K2_AS + irow * 272 + ig8 * 32 + q * 16,
                                        gb + q * 16, 16);
        };

        auto do_convert = [&](int cc) {
            const char* sAraw = sm2 + (cc & 3) * K2_STAGE;
            char* sAbf = sm2 + K2_RING + (cc & 1) * K2_ABF;
            const int4* src = reinterpret_cast<const int4*>(sAraw + irow * 272 + ig8 * 32);
            int4 v0 = src[0], v1 = src[1];
            cnt += v0.x + v0.y + v0.z + v0.w + v1.x + v1.y + v1.z + v1.w;
            uint4 w;
            w.x = pack2i(v0.x, v0.y); w.y = pack2i(v0.z, v0.w);
            w.z = pack2i(v1.x, v1.y); w.w = pack2i(v1.z, v1.w);
            *reinterpret_cast<uint4*>(sAbf + irow * 144 + ig8 * 16) = w;
        };

        issue_stage(0); __pipeline_commit();
        issue_stage(1); __pipeline_commit();
        issue_stage(2); __pipeline_commit();
        __pipeline_wait_prior(2);          // stage 0 landed (own copies)
        do_convert(0);
        __syncthreads();                   // Abf[0] + B stage 0 visible

        for (int c = 0; c < NCHI; ++c) {
            if (c + 3 < NCHI) issue_stage(c + 3);
            __pipeline_commit();
            __pipeline_wait_prior(2);      // stage c+1 landed (own copies)
            if (c + 1 < NCHI) do_convert(c + 1);

            const __nv_bfloat16* A =
                reinterpret_cast<const __nv_bfloat16*>(sm2 + K2_RING + (c & 1) * K2_ABF);
            const __nv_bfloat16* B =
                reinterpret_cast<const __nv_bfloat16*>(sm2 + (c & 3) * K2_STAGE + K2_AS);
            #pragma unroll
            for (int s = 0; s < 2; ++s) {
                const int ks = kh * 2 + s;
                wmma::fragment<wmma::matrix_a, 16, 16, 16, __nv_bfloat16, wmma::row_major> af[2];
                wmma::fragment<wmma::matrix_b, 16, 16, 16, __nv_bfloat16, wmma::row_major> bf[2];
                #pragma unroll
                for (int i = 0; i < 2; ++i)
                    wmma::load_matrix_sync(af[i], &A[(wm * 32 + i * 16) * 72 + ks * 16], 72);
                #pragma unroll
                for (int j = 0; j < 2; ++j)
                    wmma::load_matrix_sync(bf[j], &B[(ks * 16) * 136 + wn * 32 + j * 16], 136);
                #pragma unroll
                for (int i = 0; i < 2; ++i)
                    #pragma unroll
                    for (int j = 0; j < 2; ++j)
                        wmma::mma_sync(acc[i][j], af[i], bf[j], acc[i][j]);
            }
            __syncthreads();               // Abf[(c+1)&1] + stage reuse safe
        }

        atomicAdd(&sDeg[irow & 63], cnt);

        // kh partial tiles in smem (over ring slots 0-1; MMA(15) reads slot 3)
        float* sAcc0 = reinterpret_cast<float*>(sm2);
        float* sAcc1 = reinterpret_cast<float*>(sm2 + 33792);
        float* dstAcc = kh ? sAcc1 : sAcc0;
        #pragma unroll
        for (int i = 0; i < 2; ++i)
            #pragma unroll
            for (int j = 0; j < 2; ++j)
                wmma::store_matrix_sync(&dstAcc[(wm * 32 + i * 16) * 132 + wn * 32 + j * 16],
                                        acc[i][j], 132, wmma::mem_row_major);
        __syncthreads();

        // merge kh halves -> g_msgp[kq] (8192 floats; disjoint rows per item)
        float* dst = g_msgp[kq];
        #pragma unroll
        for (int i = 0; i < 16; ++i) {
            int idx = i * 512 + t;
            int row = idx >> 7, col = idx & 127;
            dst[(size_t)(m0 + row) * HID + col] =
                sAcc0[row * 132 + col] + sAcc1[row * 132 + col];
        }
        if (t < 64) g_degp[kq][m0 + t] = sDeg[t];
        __syncthreads();                   // sDeg/sAcc reads done before next item
    }
}

// ---------------------------------------------------------------------------
// K3: merge 8 partials -> msg; hid = tanh([h,msg]@W2+b2); out = hid@W3+b3.
// ---------------------------------------------------------------------------
#define K3_SMEM (4 * (32768 + 16448 + 2048 + 128 + 16 + 64))   // 205,888 B

__global__ void __launch_bounds__(256, 1) k3_actor(float* __restrict__ out,
        const float* __restrict__ W2, const float* __restrict__ b2,
        const float* __restrict__ W3, const float* __restrict__ b3) {
    extern __shared__ __align__(16) float sm[];
    float* sW2 = sm;                   // [256][128]
    float* sC  = sm + 32768;           // [64][257]; reused as hid [64][129]
    float* sW3 = sC + 16448;           // [128][16]
    float* sb2 = sW3 + 2048;
    float* sb3 = sb2 + 128;
    float* sInv = sb3 + 16;            // [64] 1/deg

    const int t  = threadIdx.x;
    const int a0 = blockIdx.x * 64;

    #pragma unroll 4
    for (int i = 0; i < 128; ++i) sW2[i * 256 + t] = W2[i * 256 + t];
    #pragma unroll
    for (int i = 0; i < 8; ++i)   sW3[i * 256 + t] = W3[i * 256 + t];
    if (t < 128) sb2[t] = b2[t];
    if (t < 16)  sb3[t] = b3[t];
    if (t < 64) {
        int d = 0;
        #pragma unroll
        for (int p = 0; p < 8; ++p) d += g_degp[p][a0 + t];
        sInv[t] = 1.0f / (float)max(d, 1);
    }
    __syncthreads();
    #pragma unroll 4
    for (int i = 0; i < 32; ++i) {
        int idx = i * 256 + t;
        int a = idx >> 7, k = idx & 127;
        size_t o = (size_t)(a0 + a) * HID + k;
        sC[a * 257 + k] = g_h[o];
        float s = 0.f;
        #pragma unroll
        for (int p = 0; p < 8; ++p) s += g_msgp[p][o];
        sC[a * 257 + 128 + k] = s * sInv[a];
    }
    __syncthreads();

    const int ar = t >> 4;
    const int cc = t & 15;
    float acc[4][8];
    #pragma unroll
    for (int j = 0; j < 4; ++j)
        #pragma unroll
        for (int i = 0; i < 8; ++i) acc[j][i] = 0.f;

    #pragma unroll 2
    for (int k = 0; k < 2 * HID; ++k) {
        float4 w0 = *reinterpret_cast<const float4*>(&sW2[k * 128 + cc * 8]);
        float4 w1 = *reinterpret_cast<const float4*>(&sW2[k * 128 + cc * 8 + 4]);
        #pragma unroll
        for (int j = 0; j < 4; ++j) {
            float cv = sC[(ar * 4 + j) * 257 + k];
            acc[j][0] = fmaf(cv, w0.x, acc[j][0]);
            acc[j][1] = fmaf(cv, w0.y, acc[j][1]);
            acc[j][2] = fmaf(cv, w0.z, acc[j][2]);
            acc[j][3] = fmaf(cv, w0.w, acc[j][3]);
            acc[j][4] = fmaf(cv, w1.x, acc[j][4]);
            acc[j][5] = fmaf(cv, w1.y, acc[j][5]);
            acc[j][6] = fmaf(cv, w1.z, acc[j][6]);
            acc[j][7] = fmaf(cv, w1.w, acc[j][7]);
        }
    }
    __syncthreads();
    float* sH = sC;                       // [64][129]
    #pragma unroll
    for (int j = 0; j < 4; ++j) {
        int a = ar * 4 + j;
        #pragma unroll
        for (int i = 0; i < 8; ++i) {
            int ccol = cc * 8 + i;
            sH[a * 129 + ccol] = tanhf(acc[j][i] + sb2[ccol]);
        }
    }
    __syncthreads();

    const int a  = t >> 2;
    const int cq = t & 3;
    float4 lg; lg.x = 0.f; lg.y = 0.f; lg.z = 0.f; lg.w = 0.f;
    #pragma unroll 8
    for (int k = 0; k < HID; ++k) {
        float hv  = sH[a * 129 + k];
        float4 w3 = *reinterpret_cast<const float4*>(&sW3[k * 16 + cq * 4]);
        lg.x = fmaf(hv, w3.x, lg.x);
        lg.y = fmaf(hv, w3.y, lg.y);
        lg.z = fmaf(hv, w3.z, lg.z);
        lg.w = fmaf(hv, w3.w, lg.w);
    }
    lg.x += sb3[cq * 4 + 0];
    lg.y += sb3[cq * 4 + 1];
    lg.z += sb3[cq * 4 + 2];
    lg.w += sb3[cq * 4 + 3];
    *reinterpret_cast<float4*>(&out[(size_t)(a0 + a) * ACTD + cq * 4]) = lg;
}

// ---------------------------------------------------------------------------
extern "C" void kernel_launch(void* const* d_in, const int* in_sizes, int n_in,
                              void* d_out, int out_size) {
    const float* obs = (const float*)d_in[0];
    const int*   adj = (const int*)  d_in[1];
    const float* W1  = (const float*)d_in[2];
    const float* b1  = (const float*)d_in[3];
    const float* W2  = (const float*)d_in[4];
    const float* b2  = (const float*)d_in[5];
    const float* W3  = (const float*)d_in[6];
    const float* b3  = (const float*)d_in[7];
    float* out = (float*)d_out;

    cudaFuncSetAttribute(k2_msg,   cudaFuncAttributeMaxDynamicSharedMemorySize, K2_SMEM);
    cudaFuncSetAttribute(k3_actor, cudaFuncAttributeMaxDynamicSharedMemorySize, K3_SMEM);

    k1_encoder<<<NAG / 8, 256>>>(obs, W1, b1);
    knop<<<1, 32>>>();                 // spacers: land ncu capture on k2_msg
    knop<<<1, 32>>>();
    k2_msg    <<<GRID2, 512, K2_SMEM>>>(adj);
    k3_actor  <<<NAG / 64, 256, K3_SMEM>>>(out, W2, b2, W3, b3);
}

// round 13
// speedup vs baseline: 1.4887x; 1.1298x over previous
#include <cuda_runtime.h>
#include <cuda_bf16.h>
#include <cuda_pipeline.h>
#include <mma.h>
#include <cstdint>

using namespace nvcuda;

#define NAG  8192
#define OBSD 64
#define HID  128
#define ACTD 16
#define NITEMS 1024        // 128 M-tiles x 8 k-quarters
#define GRID2  148         // persistent CTAs = SM count
#define NCHI   16          // chunks per item (1024 k / 64)

// Scratch (device globals: no allocations allowed)
__device__ float          g_h   [NAG * HID];       // fp32 encoder output
__device__ __nv_bfloat16  g_hb  [NAG * HID];       // bf16 h (row-major)
__device__ float          g_msgp[8][NAG * HID];    // per-k-quarter partial sums
__device__ int            g_degp[8][NAG];          // per-k-quarter degrees

// ---------------------------------------------------------------------------
// K1: h = tanh(obs @ W1 + b1) -> g_h (fp32) + g_hb (bf16).
// ---------------------------------------------------------------------------
__global__ void __launch_bounds__(256) k1_encoder(const float* __restrict__ obs,
                                                  const float* __restrict__ W1,
                                                  const float* __restrict__ b1) {
    __shared__ __align__(16) float sW1[OBSD * HID];   // 32 KB
    __shared__ float sObs[8][OBSD];
    const int t  = threadIdx.x;
    const int a0 = blockIdx.x * 8;

    #pragma unroll
    for (int i = 0; i < (OBSD * HID) / 256; ++i)
        sW1[i * 256 + t] = W1[i * 256 + t];
    #pragma unroll
    for (int i = 0; i < 2; ++i) {
        int idx = i * 256 + t;
        sObs[idx >> 6][idx & 63] = obs[(size_t)(a0 + (idx >> 6)) * OBSD + (idx & 63)];
    }
    __syncthreads();

    const int w = t >> 5, l = t & 31;
    const int agent = a0 + w;
    float acc0 = 0.f, acc1 = 0.f, acc2 = 0.f, acc3 = 0.f;
    #pragma unroll 8
    for (int k = 0; k < OBSD; ++k) {
        float o = sObs[w][k];
        float4 wv = *reinterpret_cast<const float4*>(&sW1[k * HID + l * 4]);
        acc0 = fmaf(o, wv.x, acc0);
        acc1 = fmaf(o, wv.y, acc1);
        acc2 = fmaf(o, wv.z, acc2);
        acc3 = fmaf(o, wv.w, acc3);
    }
    float4 bb = *reinterpret_cast<const float4*>(&b1[l * 4]);
    float h0 = tanhf(acc0 + bb.x);
    float h1 = tanhf(acc1 + bb.y);
    float h2 = tanhf(acc2 + bb.z);
    float h3 = tanhf(acc3 + bb.w);

    const size_t off = (size_t)agent * HID + l * 4;
    float4 hv; hv.x = h0; hv.y = h1; hv.z = h2; hv.w = h3;
    *reinterpret_cast<float4*>(&g_h[off]) = hv;
    __nv_bfloat162 p0 = __floats2bfloat162_rn(h0, h1);
    __nv_bfloat162 p1 = __floats2bfloat162_rn(h2, h3);
    *reinterpret_cast<__nv_bfloat162*>(&g_hb[off])     = p0;
    *reinterpret_cast<__nv_bfloat162*>(&g_hb[off + 2]) = p1;
}

// no-op spacers: shift ncu's captured launch (-s 5 -c 1) onto k2_msg
__global__ void knop() {}

// ---------------------------------------------------------------------------
// K2: msg partials via bf16 WMMA, persistent 148 CTAs, 16 warps.
// R13 change: A path is LDG->regs->convert->STS (no raw-A smem staging):
// removes 34KB/chunk crossbar traffic (R12 profile: L1 49.2% co-limiter).
// Ring-4 cp.async holds B ONLY (4 x 17408B). One barrier per chunk.
// Warp = wm(2 x 32 rows) x wn(4 x 32 cols) x kh(2 x 2ks).
// ---------------------------------------------------------------------------
__device__ __forceinline__ unsigned pack2i(int a, int b) {
    return (a ? 0x3F80u : 0u) | (b ? 0x3F800000u : 0u);   // two bf16 {0,1}
}

#define K2_BS    17408                     // B bf16 stage: 64 x 272 B
#define K2_RING  (4 * K2_BS)               // 69632
#define K2_ABF   9216                      // converted A: 64 x 144 B
#define K2_SMEM  (K2_RING + 2 * K2_ABF)    // 88064

__global__ void __launch_bounds__(512, 1) k2_msg(const int* __restrict__ adj) {
    extern __shared__ __align__(16) char sm2[];
    __shared__ int sDeg[64];

    const int t    = threadIdx.x;
    const int wid  = t >> 5;
    const int irow = t >> 3;       // 0..63 (A row & B k-row)
    const int ig8  = t & 7;        // 32B group within row
    const int wm   = wid & 1;          // M block (32 rows)
    const int wn   = (wid >> 1) & 3;   // N block (32 cols)
    const int kh   = wid >> 3;         // ks half (0: ks 0-1, 1: ks 2-3)

    for (int item = blockIdx.x; item < NITEMS; item += GRID2) {
        const int mt = item & 127;
        const int kq = item >> 7;
        const int m0 = mt * 64;
        const int k0 = kq * 1024;

        const int*  gA = adj + (size_t)(m0 + irow) * NAG + k0 + ig8 * 8;
        const char* gB = reinterpret_cast<const char*>(g_hb) +
                         (size_t)(k0 + irow) * (HID * 2) + ig8 * 32;

        if (t < 64) sDeg[t] = 0;
        int cnt = 0;

        wmma::fragment<wmma::accumulator, 16, 16, 16, float> acc[2][2];
        #pragma unroll
        for (int i = 0; i < 2; ++i)
            #pragma unroll
            for (int j = 0; j < 2; ++j)
                wmma::fill_fragment(acc[i][j], 0.0f);

        auto issue_stage = [&](int c) {    // B only
            char* st = sm2 + (c & 3) * K2_BS;
            const char* gb = gB + (size_t)c * 64 * 256;     // 64 k-rows x 256B
            #pragma unroll
            for (int q = 0; q < 2; ++q)
                __pipeline_memcpy_async(st + irow * 272 + ig8 * 32 + q * 16,
                                        gb + q * 16, 16);
        };

        // A register buffer: this thread's 8 int32 of the current convert chunk
        int4 a0v, a1v;
        auto ldg_a = [&](int c) {
            const int4* p = reinterpret_cast<const int4*>(gA + c * 64);
            a0v = p[0]; a1v = p[1];
        };
        auto do_convert = [&](int cc) {    // regs -> bf16 STS; counts degree
            char* sAbf = sm2 + K2_RING + (cc & 1) * K2_ABF;
            cnt += a0v.x + a0v.y + a0v.z + a0v.w + a1v.x + a1v.y + a1v.z + a1v.w;
            uint4 w;
            w.x = pack2i(a0v.x, a0v.y); w.y = pack2i(a0v.z, a0v.w);
            w.z = pack2i(a1v.x, a1v.y); w.w = pack2i(a1v.z, a1v.w);
            *reinterpret_cast<uint4*>(sAbf + irow * 144 + ig8 * 16) = w;
        };

        ldg_a(0);
        issue_stage(0); __pipeline_commit();
        issue_stage(1); __pipeline_commit();
        issue_stage(2); __pipeline_commit();
        __pipeline_wait_prior(2);          // B stage 0 landed (own copies)
        do_convert(0);
        ldg_a(1);                          // in flight across compute(0)
        __syncthreads();                   // Abf[0] + B stage 0 visible

        for (int c = 0; c < NCHI; ++c) {
            if (c + 3 < NCHI) issue_stage(c + 3);
            __pipeline_commit();
            __pipeline_wait_prior(2);      // B stage c+1 landed (own copies)
            if (c + 1 < NCHI) {
                do_convert(c + 1);         // uses regs loaded at iter c-1
                if (c + 2 < NCHI) ldg_a(c + 2);
            }

            const __nv_bfloat16* A =
                reinterpret_cast<const __nv_bfloat16*>(sm2 + K2_RING + (c & 1) * K2_ABF);
            const __nv_bfloat16* B =
                reinterpret_cast<const __nv_bfloat16*>(sm2 + (c & 3) * K2_BS);
            #pragma unroll
            for (int s = 0; s < 2; ++s) {
                const int ks = kh * 2 + s;
                wmma::fragment<wmma::matrix_a, 16, 16, 16, __nv_bfloat16, wmma::row_major> af[2];
                wmma::fragment<wmma::matrix_b, 16, 16, 16, __nv_bfloat16, wmma::row_major> bf[2];
                #pragma unroll
                for (int i = 0; i < 2; ++i)
                    wmma::load_matrix_sync(af[i], &A[(wm * 32 + i * 16) * 72 + ks * 16], 72);
                #pragma unroll
                for (int j = 0; j < 2; ++j)
                    wmma::load_matrix_sync(bf[j], &B[(ks * 16) * 136 + wn * 32 + j * 16], 136);
                #pragma unroll
                for (int i = 0; i < 2; ++i)
                    #pragma unroll
                    for (int j = 0; j < 2; ++j)
                        wmma::mma_sync(acc[i][j], af[i], bf[j], acc[i][j]);
            }
            __syncthreads();               // Abf[(c+1)&1] + B stage reuse safe
        }

        atomicAdd(&sDeg[irow], cnt);

        // kh partial tiles in smem (overlay ring; written after final barrier)
        float* sAcc0 = reinterpret_cast<float*>(sm2);
        float* sAcc1 = reinterpret_cast<float*>(sm2 + 33792);
        float* dstAcc = kh ? sAcc1 : sAcc0;
        #pragma unroll
        for (int i = 0; i < 2; ++i)
            #pragma unroll
            for (int j = 0; j < 2; ++j)
                wmma::store_matrix_sync(&dstAcc[(wm * 32 + i * 16) * 132 + wn * 32 + j * 16],
                                        acc[i][j], 132, wmma::mem_row_major);
        __syncthreads();

        // merge kh halves -> g_msgp[kq] (8192 floats; disjoint rows per item)
        float* dst = g_msgp[kq];
        #pragma unroll
        for (int i = 0; i < 16; ++i) {
            int idx = i * 512 + t;
            int row = idx >> 7, col = idx & 127;
            dst[(size_t)(m0 + row) * HID + col] =
                sAcc0[row * 132 + col] + sAcc1[row * 132 + col];
        }
        if (t < 64) g_degp[kq][m0 + t] = sDeg[t];
        __syncthreads();                   // sDeg/sAcc reads done before next item
    }
}

// ---------------------------------------------------------------------------
// K3: merge 8 partials -> msg; hid = tanh([h,msg]@W2+b2); out = hid@W3+b3.
// ---------------------------------------------------------------------------
#define K3_SMEM (4 * (32768 + 16448 + 2048 + 128 + 16 + 64))   // 205,888 B

__global__ void __launch_bounds__(256, 1) k3_actor(float* __restrict__ out,
        const float* __restrict__ W2, const float* __restrict__ b2,
        const float* __restrict__ W3, const float* __restrict__ b3) {
    extern __shared__ __align__(16) float sm[];
    float* sW2 = sm;                   // [256][128]
    float* sC  = sm + 32768;           // [64][257]; reused as hid [64][129]
    float* sW3 = sC + 16448;           // [128][16]
    float* sb2 = sW3 + 2048;
    float* sb3 = sb2 + 128;
    float* sInv = sb3 + 16;            // [64] 1/deg

    const int t  = threadIdx.x;
    const int a0 = blockIdx.x * 64;

    #pragma unroll 4
    for (int i = 0; i < 128; ++i) sW2[i * 256 + t] = W2[i * 256 + t];
    #pragma unroll
    for (int i = 0; i < 8; ++i)   sW3[i * 256 + t] = W3[i * 256 + t];
    if (t < 128) sb2[t] = b2[t];
    if (t < 16)  sb3[t] = b3[t];
    if (t < 64) {
        int d = 0;
        #pragma unroll
        for (int p = 0; p < 8; ++p) d += g_degp[p][a0 + t];
        sInv[t] = 1.0f / (float)max(d, 1);
    }
    __syncthreads();
    #pragma unroll 4
    for (int i = 0; i < 32; ++i) {
        int idx = i * 256 + t;
        int a = idx >> 7, k = idx & 127;
        size_t o = (size_t)(a0 + a) * HID + k;
        sC[a * 257 + k] = g_h[o];
        float s = 0.f;
        #pragma unroll
        for (int p = 0; p < 8; ++p) s += g_msgp[p][o];
        sC[a * 257 + 128 + k] = s * sInv[a];
    }
    __syncthreads();

    const int ar = t >> 4;
    const int cc = t & 15;
    float acc[4][8];
    #pragma unroll
    for (int j = 0; j < 4; ++j)
        #pragma unroll
        for (int i = 0; i < 8; ++i) acc[j][i] = 0.f;

    #pragma unroll 2
    for (int k = 0; k < 2 * HID; ++k) {
        float4 w0 = *reinterpret_cast<const float4*>(&sW2[k * 128 + cc * 8]);
        float4 w1 = *reinterpret_cast<const float4*>(&sW2[k * 128 + cc * 8 + 4]);
        #pragma unroll
        for (int j = 0; j < 4; ++j) {
            float cv = sC[(ar * 4 + j) * 257 + k];
            acc[j][0] = fmaf(cv, w0.x, acc[j][0]);
            acc[j][1] = fmaf(cv, w0.y, acc[j][1]);
            acc[j][2] = fmaf(cv, w0.z, acc[j][2]);
            acc[j][3] = fmaf(cv, w0.w, acc[j][3]);
            acc[j][4] = fmaf(cv, w1.x, acc[j][4]);
            acc[j][5] = fmaf(cv, w1.y, acc[j][5]);
            acc[j][6] = fmaf(cv, w1.z, acc[j][6]);
            acc[j][7] = fmaf(cv, w1.w, acc[j][7]);
        }
    }
    __syncthreads();
    float* sH = sC;                       // [64][129]
    #pragma unroll
    for (int j = 0; j < 4; ++j) {
        int a = ar * 4 + j;
        #pragma unroll
        for (int i = 0; i < 8; ++i) {
            int ccol = cc * 8 + i;
            sH[a * 129 + ccol] = tanhf(acc[j][i] + sb2[ccol]);
        }
    }
    __syncthreads();

    const int a  = t >> 2;
    const int cq = t & 3;
    float4 lg; lg.x = 0.f; lg.y = 0.f; lg.z = 0.f; lg.w = 0.f;
    #pragma unroll 8
    for (int k = 0; k < HID; ++k) {
        float hv  = sH[a * 129 + k];
        float4 w3 = *reinterpret_cast<const float4*>(&sW3[k * 16 + cq * 4]);
        lg.x = fmaf(hv, w3.x, lg.x);
        lg.y = fmaf(hv, w3.y, lg.y);
        lg.z = fmaf(hv, w3.z, lg.z);
        lg.w = fmaf(hv, w3.w, lg.w);
    }
    lg.x += sb3[cq * 4 + 0];
    lg.y += sb3[cq * 4 + 1];
    lg.z += sb3[cq * 4 + 2];
    lg.w += sb3[cq * 4 + 3];
    *reinterpret_cast<float4*>(&out[(size_t)(a0 + a) * ACTD + cq * 4]) = lg;
}

// ---------------------------------------------------------------------------
extern "C" void kernel_launch(void* const* d_in, const int* in_sizes, int n_in,
                              void* d_out, int out_size) {
    const float* obs = (const float*)d_in[0];
    const int*   adj = (const int*)  d_in[1];
    const float* W1  = (const float*)d_in[2];
    const float* b1  = (const float*)d_in[3];
    const float* W2  = (const float*)d_in[4];
    const float* b2  = (const float*)d_in[5];
    const float* W3  = (const float*)d_in[6];
    const float* b3  = (const float*)d_in[7];
    float* out = (float*)d_out;

    cudaFuncSetAttribute(k2_msg,   cudaFuncAttributeMaxDynamicSharedMemorySize, K2_SMEM);
    cudaFuncSetAttribute(k3_actor, cudaFuncAttributeMaxDynamicSharedMemorySize, K3_SMEM);

    k1_encoder<<<NAG / 8, 256>>>(obs, W1, b1);
    knop<<<1, 32>>>();                 // spacers: land ncu capture on k2_msg
    knop<<<1, 32>>>();
    k2_msg    <<<GRID2, 512, K2_SMEM>>>(adj);
    k3_actor  <<<NAG / 64, 256, K3_SMEM>>>(out, W2, b2, W3, b3);
}